// round 4
// baseline (speedup 1.0000x reference)
#include <cuda_runtime.h>
#include <cstdint>

// Problem constants (fixed by the dataset's setup_inputs)
#define S_DIM 64
#define B_DIM 32
#define N_DIM 100
#define EM_DIM 128
#define NUM_INST (S_DIM * B_DIM)       // 2048
#define M_TOT (NUM_INST * N_DIM)       // 204800
#define MISS 0x7FFFFFFF

// Scratch (allocation-free rule: __device__ globals)
__device__ int g_invy[M_TOT];      // invy[inst*N + node] = tour position of node
__device__ int g_touridx[M_TOT];   // min edge id matching tour edge (inst, i)
__device__ int g_flag_y;           // 0: cand0 is y; 1: cand1 is y
__device__ int g_ei64;             // 1: edge_index stored as int64; 0: int32

__global__ void k_reset() { g_flag_y = 0; g_ei64 = 1; }

// Detect y vs node_offset: y values are all in [0, N). node_offset (as i32
// words, whether stored i32 or i64) contains values >= N.
__global__ void k_detect_y(const int* __restrict__ cand0) {
    int t = blockIdx.x * blockDim.x + threadIdx.x;
    if (t >= M_TOT) return;
    int v = cand0[t];
    if (v < 0 || v >= N_DIM) g_flag_y = 1;   // benign race: all writers write 1
}

// Detect edge_index dtype: int64 little-endian with values < 2^31 means every
// odd 32-bit word is zero. Any nonzero odd word in the first 4096 -> int32.
__global__ void k_detect_ei(const int* __restrict__ ei32) {
    int t = blockIdx.x * blockDim.x + threadIdx.x;
    if (t >= 4096) return;
    if (ei32[2 * t + 1] != 0) g_ei64 = 0;
}

// Init touridx to MISS and build inverse tour permutation.
__global__ void k_build_inv(const int* __restrict__ cand0,
                            const int* __restrict__ cand1) {
    const int* y = g_flag_y ? cand1 : cand0;
    int t = blockIdx.x * blockDim.x + threadIdx.x;
    if (t >= M_TOT) return;
    g_touridx[t] = MISS;
    int inst = t / N_DIM;
    int node = y[t];                       // permutation of 0..N-1 per instance
    if (node >= 0 && node < N_DIM)
        g_invy[inst * N_DIM + node] = t - inst * N_DIM;
}

// For every edge: is it tour edge i of its instance (src at tour position i,
// dst at position (i+1)%N)? Keep the MINIMUM original edge index (matches
// stable argsort + leftmost searchsorted on duplicate keys).
__global__ void k_match(const void* __restrict__ ei_raw,
                        const int* __restrict__ cand0,
                        const int* __restrict__ cand1, int E) {
    const int* y = g_flag_y ? cand1 : cand0;
    int e = blockIdx.x * blockDim.x + threadIdx.x;
    if (e >= E) return;
    long long src, dst;
    if (g_ei64) {
        const long long* ei = (const long long*)ei_raw;
        src = ei[e];
        dst = ei[E + e];
    } else {
        const int* ei = (const int*)ei_raw;
        src = ei[e];
        dst = ei[E + e];
    }
    long long instl = src / N_DIM;
    if (instl < 0 || instl >= NUM_INST) return;
    int inst = (int)instl;
    int ls = (int)(src - (long long)inst * N_DIM);
    if (dst / N_DIM != instl) return;      // edges are intra-instance
    int ld = (int)(dst - (long long)inst * N_DIM);
    int i = g_invy[inst * N_DIM + ls];     // tour position of src
    int inext = (i + 1 == N_DIM) ? 0 : i + 1;
    if (y[inst * N_DIM + inext] == ld) {
        atomicMin(&g_touridx[inst * N_DIM + i], e);
    }
}

// One block per instance (128 threads = one EM lane each). Stage the 100
// resolved edge ids into shared, then each thread accumulates its EM lane
// over 100 rows (each row read = 512B fully coalesced across the block).
__global__ void k_gather(const float* __restrict__ emb, float* __restrict__ out) {
    int inst = blockIdx.x;
    int t = threadIdx.x;
    __shared__ int sidx[N_DIM];
    if (t < N_DIM) sidx[t] = g_touridx[inst * N_DIM + t];
    __syncthreads();

    float acc = 0.0f;
    #pragma unroll 4
    for (int i = 0; i < N_DIM; i++) {
        int id = sidx[i];
        if (id != MISS)
            acc += emb[(size_t)id * EM_DIM + t];
    }
    out[(size_t)inst * EM_DIM + t] = acc * (1.0f / N_DIM);
}

extern "C" void kernel_launch(void* const* d_in, const int* in_sizes, int n_in,
                              void* d_out, int out_size) {
    // Identify inputs by element count, order- and dtype-agnostic:
    //   edge_emb = largest buffer, edge_index = second largest,
    //   y / node_offset = the remaining two (disambiguated on device).
    int idx_emb = -1, idx_ei = -1, idx_s0 = -1, idx_s1 = -1;
    long long mx = -1;
    for (int i = 0; i < n_in; i++)
        if ((long long)in_sizes[i] > mx) { mx = in_sizes[i]; idx_emb = i; }
    long long mx2 = -1;
    for (int i = 0; i < n_in; i++) {
        if (i == idx_emb) continue;
        if ((long long)in_sizes[i] > mx2) { mx2 = in_sizes[i]; idx_ei = i; }
    }
    for (int i = 0; i < n_in; i++) {
        if (i == idx_emb || i == idx_ei) continue;
        if (idx_s0 < 0) idx_s0 = i; else idx_s1 = i;
    }

    const float* emb   = (const float*)d_in[idx_emb];
    const void*  ei    = d_in[idx_ei];
    const int*   cand0 = (const int*)d_in[idx_s0];
    const int*   cand1 = (const int*)d_in[idx_s1];
    float*       out   = (float*)d_out;

    // E from edge_emb element count: immune to i64-vs-i32 size conventions.
    int E = in_sizes[idx_emb] / EM_DIM;    // 409600

    k_reset<<<1, 1>>>();
    k_detect_y<<<(M_TOT + 255) / 256, 256>>>(cand0);
    k_detect_ei<<<(4096 + 255) / 256, 256>>>((const int*)ei);
    k_build_inv<<<(M_TOT + 255) / 256, 256>>>(cand0, cand1);
    k_match<<<(E + 255) / 256, 256>>>(ei, cand0, cand1, E);
    k_gather<<<NUM_INST, EM_DIM>>>(emb, out);
}

// round 5
// speedup vs baseline: 1.4474x; 1.4474x over previous
#include <cuda_runtime.h>
#include <cstdint>

// Problem constants (fixed by the dataset's setup_inputs)
#define S_DIM 64
#define B_DIM 32
#define N_DIM 100
#define EM_DIM 128
#define NUM_INST (S_DIM * B_DIM)       // 2048
#define M_TOT (NUM_INST * N_DIM)       // 204800
#define MISS 0x7FFFFFFF

// Scratch (allocation-free rule: __device__ globals).
// Flags are deterministic: static init = the value they hold if no detection
// fires; detection only ever writes the single data-determined value, so the
// state is identical on every graph replay (no reset kernel needed).
__device__ int g_invy0[M_TOT];     // inverse perm assuming cand0 is y
__device__ int g_invy1[M_TOT];     // inverse perm assuming cand1 is y
__device__ int g_touridx[M_TOT];   // min edge id matching tour edge (inst, i)
__device__ int g_flag_y = 0;       // 0: cand0 is y; 1: cand1 is y
__device__ int g_ei64  = 1;        // 1: edge_index stored int64; 0: int32

// Kernel A: fused detect + init + build-both-inverse-permutations.
//  - ei dtype: int64 little-endian with values < 2^31 => odd 32-bit words all 0.
//  - y vs node_offset: y values all in [0, N); node_offset (as i32 words under
//    either storage) contains values >= N.
//  - build invy for BOTH candidates (range-guarded); match selects by flag.
__global__ void k_prep(const int* __restrict__ cand0,
                       const int* __restrict__ cand1,
                       const int* __restrict__ ei32) {
    unsigned t = blockIdx.x * blockDim.x + threadIdx.x;
    if (t < 4096u) {
        if (ei32[2 * t + 1] != 0) g_ei64 = 0;
    }
    if (t >= M_TOT) return;
    g_touridx[t] = MISS;
    unsigned inst = t / N_DIM;
    int pos = (int)(t - inst * N_DIM);
    int v0 = cand0[t];
    int v1 = cand1[t];
    if ((unsigned)v0 < N_DIM) g_invy0[inst * N_DIM + v0] = pos;
    else                      g_flag_y = 1;          // cand0 can't be y
    if ((unsigned)v1 < N_DIM) g_invy1[inst * N_DIM + v1] = pos;
}

// Kernel B: for every edge, is it tour edge i of its instance (src at tour
// position i, dst at position (i+1)%N)? Keep the MINIMUM original edge index
// (matches stable argsort + leftmost searchsorted on duplicate keys).
__global__ void k_match(const void* __restrict__ ei_raw,
                        const int* __restrict__ cand0,
                        const int* __restrict__ cand1, int E) {
    int e = blockIdx.x * blockDim.x + threadIdx.x;
    if (e >= E) return;
    const int flag = g_flag_y;
    const int* __restrict__ y    = flag ? cand1 : cand0;
    const int* __restrict__ invy = flag ? g_invy1 : g_invy0;

    unsigned src, dst;
    if (g_ei64) {
        const long long* ei = (const long long*)ei_raw;
        long long s = ei[e], d = ei[E + e];
        if ((unsigned long long)s >= M_TOT || (unsigned long long)d >= M_TOT) return;
        src = (unsigned)s; dst = (unsigned)d;
    } else {
        const int* ei = (const int*)ei_raw;
        int s = ei[e], d = ei[E + e];
        if ((unsigned)s >= M_TOT || (unsigned)d >= M_TOT) return;
        src = (unsigned)s; dst = (unsigned)d;
    }
    unsigned inst = src / N_DIM;            // u32 const-div -> mulhi
    unsigned ls   = src - inst * N_DIM;
    if (dst / N_DIM != inst) return;        // edges are intra-instance
    unsigned ld   = dst - inst * N_DIM;
    int i = invy[inst * N_DIM + ls];        // tour position of src
    int inext = (i + 1 == N_DIM) ? 0 : i + 1;
    if (y[inst * N_DIM + inext] == (int)ld) {
        atomicMin(&g_touridx[inst * N_DIM + i], e);
    }
}

// Kernel C: one block (128 thr = 4 warps) per instance. Each warp takes 25 of
// the 100 tour edges; each thread loads one float4 => a warp covers a full
// 512B row per iteration (perfectly coalesced). Partials reduced via shared.
__global__ void k_gather(const float4* __restrict__ emb,
                         float4* __restrict__ out) {
    int inst = blockIdx.x;
    int w = threadIdx.x >> 5;
    int l = threadIdx.x & 31;
    __shared__ int sidx[N_DIM];
    __shared__ float4 spart[4][32];

    if (threadIdx.x < N_DIM) sidx[threadIdx.x] = g_touridx[inst * N_DIM + threadIdx.x];
    __syncthreads();

    float4 acc = make_float4(0.f, 0.f, 0.f, 0.f);
    int base = w * 25;
    #pragma unroll 5
    for (int i = 0; i < 25; i++) {
        int id = sidx[base + i];
        if (id != MISS) {
            float4 v = emb[(size_t)id * (EM_DIM / 4) + l];
            acc.x += v.x; acc.y += v.y; acc.z += v.z; acc.w += v.w;
        }
    }
    spart[w][l] = acc;
    __syncthreads();

    if (w == 0) {
        float4 a = spart[0][l], b = spart[1][l], c = spart[2][l], d = spart[3][l];
        const float s = 1.0f / N_DIM;
        float4 r;
        r.x = (a.x + b.x + c.x + d.x) * s;
        r.y = (a.y + b.y + c.y + d.y) * s;
        r.z = (a.z + b.z + c.z + d.z) * s;
        r.w = (a.w + b.w + c.w + d.w) * s;
        out[(size_t)inst * (EM_DIM / 4) + l] = r;
    }
}

extern "C" void kernel_launch(void* const* d_in, const int* in_sizes, int n_in,
                              void* d_out, int out_size) {
    // Identify inputs by element count (order- and dtype-agnostic):
    //   edge_emb = largest, edge_index = second largest,
    //   y / node_offset = remaining two (disambiguated on device).
    int idx_emb = -1, idx_ei = -1, idx_s0 = -1, idx_s1 = -1;
    long long mx = -1;
    for (int i = 0; i < n_in; i++)
        if ((long long)in_sizes[i] > mx) { mx = in_sizes[i]; idx_emb = i; }
    long long mx2 = -1;
    for (int i = 0; i < n_in; i++) {
        if (i == idx_emb) continue;
        if ((long long)in_sizes[i] > mx2) { mx2 = in_sizes[i]; idx_ei = i; }
    }
    for (int i = 0; i < n_in; i++) {
        if (i == idx_emb || i == idx_ei) continue;
        if (idx_s0 < 0) idx_s0 = i; else idx_s1 = i;
    }

    const float4* emb   = (const float4*)d_in[idx_emb];
    const void*   ei    = d_in[idx_ei];
    const int*    cand0 = (const int*)d_in[idx_s0];
    const int*    cand1 = (const int*)d_in[idx_s1];
    float4*       out   = (float4*)d_out;

    // E from edge_emb element count: immune to i64-vs-i32 size conventions.
    int E = in_sizes[idx_emb] / EM_DIM;    // 409600

    k_prep<<<(M_TOT + 255) / 256, 256>>>(cand0, cand1, (const int*)ei);
    k_match<<<(E + 255) / 256, 256>>>(ei, cand0, cand1, E);
    k_gather<<<NUM_INST, EM_DIM>>>(emb, out);
}

// round 6
// speedup vs baseline: 1.4491x; 1.0012x over previous
#include <cuda_runtime.h>
#include <cstdint>

// Problem constants (fixed by the dataset's setup_inputs)
#define S_DIM 64
#define B_DIM 32
#define N_DIM 100
#define EM_DIM 128
#define NUM_INST (S_DIM * B_DIM)       // 2048
#define M_TOT (NUM_INST * N_DIM)       // 204800
#define MISS 0x7FFFFFFF

// Scratch (allocation-free rule: __device__ globals).
// Flags are deterministic: static init = value held if no detection fires;
// detection only ever writes the single data-determined value, so state is
// identical on every graph replay (no reset kernel needed).
__device__ int g_invy0[M_TOT];     // inverse perm assuming cand0 is y
__device__ int g_invy1[M_TOT];     // inverse perm assuming cand1 is y
__device__ int g_touridx[M_TOT];   // min edge id matching tour edge (inst, i)
__device__ int g_flag_y = 0;       // 0: cand0 is y; 1: cand1 is y
__device__ int g_ei64  = 1;        // 1: edge_index stored int64; 0: int32

// Kernel A (x4 vectorized): fused detect + init + build both inverse perms.
//  - ei dtype: i64 little-endian with values < 2^31 => odd 32-bit words all 0.
//  - y vs node_offset: y values all in [0, N); node_offset contains >= N.
__global__ void k_prep(const int4* __restrict__ cand0,
                       const int4* __restrict__ cand1,
                       const int*  __restrict__ ei32) {
    unsigned t = blockIdx.x * blockDim.x + threadIdx.x;     // 0 .. M_TOT/4-1
    if (t < 4096u) {
        if (ei32[2 * t + 1] != 0) g_ei64 = 0;
    }
    if (t >= M_TOT / 4) return;

    int4 v0 = cand0[t];
    int4 v1 = cand1[t];
    ((int4*)g_touridx)[t] = make_int4(MISS, MISS, MISS, MISS);

    unsigned base = t * 4;
    unsigned inst = base / N_DIM;          // const-div -> mulhi
    unsigned pos  = base - inst * N_DIM;   // 4t mod 100 is even, <= 96: all 4
                                           // elements stay in the same instance
    unsigned ib = inst * N_DIM;
    // cand0 branch (also y-detection)
    if ((unsigned)v0.x < N_DIM) g_invy0[ib + v0.x] = pos;     else g_flag_y = 1;
    if ((unsigned)v0.y < N_DIM) g_invy0[ib + v0.y] = pos + 1; else g_flag_y = 1;
    if ((unsigned)v0.z < N_DIM) g_invy0[ib + v0.z] = pos + 2; else g_flag_y = 1;
    if ((unsigned)v0.w < N_DIM) g_invy0[ib + v0.w] = pos + 3; else g_flag_y = 1;
    // cand1 branch
    if ((unsigned)v1.x < N_DIM) g_invy1[ib + v1.x] = pos;
    if ((unsigned)v1.y < N_DIM) g_invy1[ib + v1.y] = pos + 1;
    if ((unsigned)v1.z < N_DIM) g_invy1[ib + v1.z] = pos + 2;
    if ((unsigned)v1.w < N_DIM) g_invy1[ib + v1.w] = pos + 3;
}

// Per-edge match test (shared by both dtype paths).
__device__ __forceinline__ void match_one(unsigned src, unsigned dst, int e,
                                          const int* __restrict__ y,
                                          const int* __restrict__ invy) {
    if (src >= M_TOT || dst >= M_TOT) return;
    unsigned inst = src / N_DIM;
    unsigned ls   = src - inst * N_DIM;
    if (dst / N_DIM != inst) return;       // edges are intra-instance
    unsigned ld   = dst - inst * N_DIM;
    int i = invy[inst * N_DIM + ls];       // tour position of src
    int inext = (i + 1 == N_DIM) ? 0 : i + 1;
    if (y[inst * N_DIM + inext] == (int)ld)
        atomicMin(&g_touridx[inst * N_DIM + i], e);
}

// Kernel B (x2 vectorized): min-original-edge-index match (matches stable
// argsort + leftmost searchsorted on duplicate keys).
__global__ void k_match(const void* __restrict__ ei_raw,
                        const int* __restrict__ cand0,
                        const int* __restrict__ cand1, int E) {
    int p = blockIdx.x * blockDim.x + threadIdx.x;   // pair index
    int e = p * 2;
    if (e >= E) return;
    const int flag = g_flag_y;
    const int* __restrict__ y    = flag ? cand1 : cand0;
    const int* __restrict__ invy = flag ? g_invy1 : g_invy0;

    if (g_ei64) {
        const longlong2* ei = (const longlong2*)ei_raw;
        longlong2 s = ei[p];
        longlong2 d = ei[E / 2 + p];
        match_one((unsigned)(unsigned long long)s.x,
                  (unsigned)(unsigned long long)d.x, e, y, invy);
        match_one((unsigned)(unsigned long long)s.y,
                  (unsigned)(unsigned long long)d.y, e + 1, y, invy);
    } else {
        const int2* ei = (const int2*)ei_raw;
        int2 s = ei[p];
        int2 d = ei[E / 2 + p];
        match_one((unsigned)s.x, (unsigned)d.x, e, y, invy);
        match_one((unsigned)s.y, (unsigned)d.y, e + 1, y, invy);
    }
}

// Kernel C: one block (128 thr = 4 warps) per instance. Each warp takes 25 of
// the 100 tour edges; each thread loads one float4 => a warp covers a full
// 512B row per iteration (perfectly coalesced). Partials reduced via shared.
__global__ void k_gather(const float4* __restrict__ emb,
                         float4* __restrict__ out) {
    int inst = blockIdx.x;
    int w = threadIdx.x >> 5;
    int l = threadIdx.x & 31;
    __shared__ int sidx[N_DIM];
    __shared__ float4 spart[4][32];

    if (threadIdx.x < N_DIM) sidx[threadIdx.x] = g_touridx[inst * N_DIM + threadIdx.x];
    __syncthreads();

    float4 acc = make_float4(0.f, 0.f, 0.f, 0.f);
    int base = w * 25;
    #pragma unroll
    for (int i = 0; i < 25; i++) {
        int id = sidx[base + i];
        if (id != MISS) {
            float4 v = emb[(size_t)id * (EM_DIM / 4) + l];
            acc.x += v.x; acc.y += v.y; acc.z += v.z; acc.w += v.w;
        }
    }
    spart[w][l] = acc;
    __syncthreads();

    if (w == 0) {
        float4 a = spart[0][l], b = spart[1][l], c = spart[2][l], d = spart[3][l];
        const float s = 1.0f / N_DIM;
        float4 r;
        r.x = (a.x + b.x + c.x + d.x) * s;
        r.y = (a.y + b.y + c.y + d.y) * s;
        r.z = (a.z + b.z + c.z + d.z) * s;
        r.w = (a.w + b.w + c.w + d.w) * s;
        out[(size_t)inst * (EM_DIM / 4) + l] = r;
    }
}

extern "C" void kernel_launch(void* const* d_in, const int* in_sizes, int n_in,
                              void* d_out, int out_size) {
    // Identify inputs by element count (order- and dtype-agnostic):
    //   edge_emb = largest, edge_index = second largest,
    //   y / node_offset = remaining two (disambiguated on device).
    int idx_emb = -1, idx_ei = -1, idx_s0 = -1, idx_s1 = -1;
    long long mx = -1;
    for (int i = 0; i < n_in; i++)
        if ((long long)in_sizes[i] > mx) { mx = in_sizes[i]; idx_emb = i; }
    long long mx2 = -1;
    for (int i = 0; i < n_in; i++) {
        if (i == idx_emb) continue;
        if ((long long)in_sizes[i] > mx2) { mx2 = in_sizes[i]; idx_ei = i; }
    }
    for (int i = 0; i < n_in; i++) {
        if (i == idx_emb || i == idx_ei) continue;
        if (idx_s0 < 0) idx_s0 = i; else idx_s1 = i;
    }

    const float4* emb   = (const float4*)d_in[idx_emb];
    const void*   ei    = d_in[idx_ei];
    const int4*   cand0 = (const int4*)d_in[idx_s0];
    const int4*   cand1 = (const int4*)d_in[idx_s1];
    float4*       out   = (float4*)d_out;

    // E from edge_emb element count: immune to i64-vs-i32 size conventions.
    int E = in_sizes[idx_emb] / EM_DIM;    // 409600

    k_prep<<<(M_TOT / 4 + 255) / 256, 256>>>(cand0, cand1, (const int*)ei);
    k_match<<<(E / 2 + 255) / 256, 256>>>(ei, (const int*)cand0, (const int*)cand1, E);
    k_gather<<<NUM_INST, EM_DIM>>>(emb, out);
}

// round 8
// speedup vs baseline: 1.4611x; 1.0083x over previous
#include <cuda_runtime.h>
#include <cstdint>

// Problem constants (fixed by the dataset's setup_inputs)
#define S_DIM 64
#define B_DIM 32
#define N_DIM 100
#define EM_DIM 128
#define NUM_INST (S_DIM * B_DIM)       // 2048
#define M_TOT (NUM_INST * N_DIM)       // 204800
#define MISS 0x7FFFFFFF

// Scratch (allocation-free rule: __device__ globals).
// g_ei64 is deterministic across graph replays: static init = value held if
// detection never fires; detection only writes the one data-determined value.
__device__ int g_invy[M_TOT];      // invy[inst*N + node] = tour position of node
__device__ int g_touridx[M_TOT];   // min edge id matching tour edge (inst, i)
__device__ int g_ei64 = 1;         // 1: edge_index stored int64; 0: int32

// Kernel A: init touridx + build the ONE inverse tour permutation.
// Per-tile y-vs-node_offset detection (no global flag needed):
//   node_offset[t] = t, so an int4 tile of it is exactly {b,b+1,b+2,b+3}
//   (i32 storage) or has both odd words == 0 (i64 word-view). y is a
//   per-instance permutation: 0 appears at most once per instance and a tile
//   never spans instances (4t mod 100 <= 96), so y can't match either pattern.
__global__ void k_prep(const int4* __restrict__ c0,
                       const int4* __restrict__ c1,
                       const int*  __restrict__ ei32) {
    unsigned t = blockIdx.x * blockDim.x + threadIdx.x;     // 0 .. M_TOT/4-1
    if (t < 4096u) {
        if (ei32[2 * t + 1] != 0) g_ei64 = 0;               // i32 edge_index
    }
    if (t >= M_TOT / 4) return;

    int4 v0 = c0[t];
    int4 v1 = c1[t];
    ((int4*)g_touridx)[t] = make_int4(MISS, MISS, MISS, MISS);

    int base = (int)(t * 4);
    bool c0_is_nodeoffset =
        (v0.y == 0 && v0.w == 0) ||                          // i64 word-view
        (v0.x == base && v0.y == base + 1 &&
         v0.z == base + 2 && v0.w == base + 3);              // i32 arange
    int4 v = c0_is_nodeoffset ? v1 : v0;

    unsigned inst = (unsigned)base / N_DIM;                  // const-div
    int pos = base - (int)(inst * N_DIM);
    int* __restrict__ ib = g_invy + inst * N_DIM;
    if ((unsigned)v.x < N_DIM) ib[v.x] = pos;
    if ((unsigned)v.y < N_DIM) ib[v.y] = pos + 1;
    if ((unsigned)v.z < N_DIM) ib[v.z] = pos + 2;
    if ((unsigned)v.w < N_DIM) ib[v.w] = pos + 3;
}

// Per-edge test: edge (src,dst) is tour edge i of its instance iff
// invy[dst] == (invy[src]+1) % N, with i = invy[src]. Since invy is laid out
// [inst*N + node] and src = inst*N + ls, both lookups are direct: g_invy[src],
// g_invy[dst] — two INDEPENDENT loads (no dependent chain). Keep MINIMUM
// original edge index (stable argsort + leftmost searchsorted semantics).
__device__ __forceinline__ void match_one(unsigned src, unsigned dst, int e) {
    if (src >= M_TOT || dst >= M_TOT) return;
    unsigned inst = src / N_DIM;
    if (dst / N_DIM != inst) return;        // edges are intra-instance
    int pi = g_invy[src];
    int pd = g_invy[dst];
    int inext = (pi + 1 == N_DIM) ? 0 : pi + 1;
    if (pd == inext)
        atomicMin(&g_touridx[inst * N_DIM + pi], e);
}

// Kernel B (x2 vectorized over edges).
__global__ void k_match(const void* __restrict__ ei_raw, int E) {
    int p = blockIdx.x * blockDim.x + threadIdx.x;   // pair index
    int e = p * 2;
    if (e >= E) return;

    if (g_ei64) {
        const longlong2* ei = (const longlong2*)ei_raw;
        longlong2 s = ei[p];
        longlong2 d = ei[E / 2 + p];
        match_one((unsigned)(unsigned long long)s.x,
                  (unsigned)(unsigned long long)d.x, e);
        match_one((unsigned)(unsigned long long)s.y,
                  (unsigned)(unsigned long long)d.y, e + 1);
    } else {
        const int2* ei = (const int2*)ei_raw;
        int2 s = ei[p];
        int2 d = ei[E / 2 + p];
        match_one((unsigned)s.x, (unsigned)d.x, e);
        match_one((unsigned)s.y, (unsigned)d.y, e + 1);
    }
}

// Kernel C: one block (128 thr = 4 warps) per instance. Each warp takes 25 of
// the 100 tour edges; each thread loads one float4 => a warp covers a full
// 512B row per iteration (perfectly coalesced). Partials reduced via shared.
__global__ void k_gather(const float4* __restrict__ emb,
                         float4* __restrict__ out) {
    int inst = blockIdx.x;
    int w = threadIdx.x >> 5;
    int l = threadIdx.x & 31;
    __shared__ int sidx[N_DIM];
    __shared__ float4 spart[4][32];

    if (threadIdx.x < N_DIM) sidx[threadIdx.x] = g_touridx[inst * N_DIM + threadIdx.x];
    __syncthreads();

    float4 acc = make_float4(0.f, 0.f, 0.f, 0.f);
    int base = w * 25;
    #pragma unroll
    for (int i = 0; i < 25; i++) {
        int id = sidx[base + i];
        if (id != MISS) {
            float4 v = emb[(size_t)id * (EM_DIM / 4) + l];
            acc.x += v.x; acc.y += v.y; acc.z += v.z; acc.w += v.w;
        }
    }
    spart[w][l] = acc;
    __syncthreads();

    if (w == 0) {
        float4 a = spart[0][l], b = spart[1][l], c = spart[2][l], d = spart[3][l];
        const float s = 1.0f / N_DIM;
        float4 r;
        r.x = (a.x + b.x + c.x + d.x) * s;
        r.y = (a.y + b.y + c.y + d.y) * s;
        r.z = (a.z + b.z + c.z + d.z) * s;
        r.w = (a.w + b.w + c.w + d.w) * s;
        out[(size_t)inst * (EM_DIM / 4) + l] = r;
    }
}

extern "C" void kernel_launch(void* const* d_in, const int* in_sizes, int n_in,
                              void* d_out, int out_size) {
    // Identify inputs by element count (order- and dtype-agnostic):
    //   edge_emb = largest, edge_index = second largest,
    //   y / node_offset = remaining two (disambiguated per-tile on device).
    int idx_emb = -1, idx_ei = -1, idx_s0 = -1, idx_s1 = -1;
    long long mx = -1;
    for (int i = 0; i < n_in; i++)
        if ((long long)in_sizes[i] > mx) { mx = in_sizes[i]; idx_emb = i; }
    long long mx2 = -1;
    for (int i = 0; i < n_in; i++) {
        if (i == idx_emb) continue;
        if ((long long)in_sizes[i] > mx2) { mx2 = in_sizes[i]; idx_ei = i; }
    }
    for (int i = 0; i < n_in; i++) {
        if (i == idx_emb || i == idx_ei) continue;
        if (idx_s0 < 0) idx_s0 = i; else idx_s1 = i;
    }

    const float4* emb   = (const float4*)d_in[idx_emb];
    const void*   ei    = d_in[idx_ei];
    const int4*   cand0 = (const int4*)d_in[idx_s0];
    const int4*   cand1 = (const int4*)d_in[idx_s1];
    float4*       out   = (float4*)d_out;

    // E from edge_emb element count: immune to i64-vs-i32 size conventions.
    int E = in_sizes[idx_emb] / EM_DIM;    // 409600

    k_prep<<<(M_TOT / 4 + 127) / 128, 128>>>(cand0, cand1, (const int*)ei);
    k_match<<<(E / 2 + 255) / 256, 256>>>(ei, E);
    k_gather<<<NUM_INST, EM_DIM>>>(emb, out);
}

// round 13
// speedup vs baseline: 1.5624x; 1.0694x over previous
#include <cuda_runtime.h>
#include <cstdint>

// Problem constants (fixed by the dataset's setup_inputs)
#define S_DIM 64
#define B_DIM 32
#define N_DIM 100
#define EM_DIM 128
#define NUM_INST (S_DIM * B_DIM)       // 2048
#define M_TOT (NUM_INST * N_DIM)       // 204800
#define MISS 0x7FFFFFFF

// Scratch (allocation-free rule: __device__ globals).
// g_ei64 is deterministic across graph replays: static init = value held if
// detection never fires; detection only writes the one data-determined value.
__device__ int g_tournext[M_TOT];  // tournext[g_node] = global id of tour successor
__device__ int g_minedge[M_TOT];   // min edge id whose (src,dst) == (node, tournext[node])
__device__ int g_ei64 = 1;         // 1: edge_index stored int64; 0: int32

// Kernel A: init minedge + build the successor map from y.
// Per-tile y-vs-node_offset detection (no global flag needed):
//   node_offset[t] = t, so an int4 tile of it is exactly {b,b+1,b+2,b+3}
//   (i32 storage) or has both odd words == 0 (i64 word-view). y is a
//   per-instance permutation (contains 0 at most once per instance, tile never
//   spans instances since 4t mod 100 <= 96), so y matches neither pattern.
__global__ void k_prep(const int4* __restrict__ c0,
                       const int4* __restrict__ c1,
                       const int*  __restrict__ ei32) {
    unsigned t = blockIdx.x * blockDim.x + threadIdx.x;     // 0 .. M_TOT/4-1
    if (t < 4096u) {
        if (ei32[2 * t + 1] != 0) g_ei64 = 0;               // i32 edge_index
    }
    if (t >= M_TOT / 4) return;

    int4 v0 = c0[t];
    int4 v1 = c1[t];
    ((int4*)g_minedge)[t] = make_int4(MISS, MISS, MISS, MISS);

    int base = (int)(t * 4);
    bool c0_is_nodeoffset =
        (v0.y == 0 && v0.w == 0) ||                          // i64 word-view
        (v0.x == base && v0.y == base + 1 &&
         v0.z == base + 2 && v0.w == base + 3);              // i32 arange
    const int* __restrict__ ysel =
        c0_is_nodeoffset ? (const int*)c1 : (const int*)c0;
    int4 v = c0_is_nodeoffset ? v1 : v0;

    unsigned inst = (unsigned)base / N_DIM;                  // const-div -> mulhi
    int pos   = base - (int)(inst * N_DIM);                  // even, <= 96
    int ibase = (int)(inst * N_DIM);
    // Successor of the node at tile slot k is the node at slot k+1; the last
    // slot's successor is y[base+4], wrapping to y[ibase] when pos == 96
    // (i.e. slot pos+3 == 99 is the tour end).
    int nxt = (pos == 96) ? ysel[ibase] : ysel[base + 4];

    if ((unsigned)v.x < N_DIM) g_tournext[ibase + v.x] = ibase + v.y;
    if ((unsigned)v.y < N_DIM) g_tournext[ibase + v.y] = ibase + v.z;
    if ((unsigned)v.z < N_DIM) g_tournext[ibase + v.z] = ibase + v.w;
    if ((unsigned)v.w < N_DIM) g_tournext[ibase + v.w] = ibase + nxt;
}

// Per-edge test: edge e=(src,dst) is a tour edge iff tournext[src] == dst.
// Keep the MINIMUM original edge index per tour edge (matches stable argsort
// + leftmost searchsorted on duplicate keys). Slot keyed directly by src node.
// No integer divides, one independent 4B load (tournext is L2-resident).
__device__ __forceinline__ void match_one(unsigned src, unsigned dst, int e) {
    if (src >= M_TOT) return;
    if (g_tournext[src] == (int)dst)        // dst >= M_TOT can never match
        atomicMin(&g_minedge[src], e);
}

// Kernel B (x2 vectorized over edges).
__global__ void k_match(const void* __restrict__ ei_raw, int E) {
    int p = blockIdx.x * blockDim.x + threadIdx.x;   // pair index
    int e = p * 2;
    if (e >= E) return;

    if (g_ei64) {
        const longlong2* ei = (const longlong2*)ei_raw;
        longlong2 s = ei[p];
        longlong2 d = ei[E / 2 + p];
        match_one((unsigned)(unsigned long long)s.x,
                  (unsigned)(unsigned long long)d.x, e);
        match_one((unsigned)(unsigned long long)s.y,
                  (unsigned)(unsigned long long)d.y, e + 1);
    } else {
        const int2* ei = (const int2*)ei_raw;
        int2 s = ei[p];
        int2 d = ei[E / 2 + p];
        match_one((unsigned)s.x, (unsigned)d.x, e);
        match_one((unsigned)s.y, (unsigned)d.y, e + 1);
    }
}

// Kernel C: one block (128 thr = 4 warps) per instance. Slots are keyed by
// node id instead of tour position — a bijection, and the mean is
// order-invariant, so the result is identical. Each warp takes 25 of the 100
// slots; each thread loads one float4 => a warp covers a full 512B row per
// iteration (perfectly coalesced). Partials reduced via shared.
__global__ void k_gather(const float4* __restrict__ emb,
                         float4* __restrict__ out) {
    int inst = blockIdx.x;
    int w = threadIdx.x >> 5;
    int l = threadIdx.x & 31;
    __shared__ int sidx[N_DIM];
    __shared__ float4 spart[4][32];

    if (threadIdx.x < N_DIM) sidx[threadIdx.x] = g_minedge[inst * N_DIM + threadIdx.x];
    __syncthreads();

    float4 acc = make_float4(0.f, 0.f, 0.f, 0.f);
    int base = w * 25;
    #pragma unroll
    for (int i = 0; i < 25; i++) {
        int id = sidx[base + i];
        if (id != MISS) {
            float4 v = emb[(size_t)id * (EM_DIM / 4) + l];
            acc.x += v.x; acc.y += v.y; acc.z += v.z; acc.w += v.w;
        }
    }
    spart[w][l] = acc;
    __syncthreads();

    if (w == 0) {
        float4 a = spart[0][l], b = spart[1][l], c = spart[2][l], d = spart[3][l];
        const float s = 1.0f / N_DIM;
        float4 r;
        r.x = (a.x + b.x + c.x + d.x) * s;
        r.y = (a.y + b.y + c.y + d.y) * s;
        r.z = (a.z + b.z + c.z + d.z) * s;
        r.w = (a.w + b.w + c.w + d.w) * s;
        out[(size_t)inst * (EM_DIM / 4) + l] = r;
    }
}

extern "C" void kernel_launch(void* const* d_in, const int* in_sizes, int n_in,
                              void* d_out, int out_size) {
    // Identify inputs by element count (order- and dtype-agnostic):
    //   edge_emb = largest, edge_index = second largest,
    //   y / node_offset = remaining two (disambiguated per-tile on device).
    int idx_emb = -1, idx_ei = -1, idx_s0 = -1, idx_s1 = -1;
    long long mx = -1;
    for (int i = 0; i < n_in; i++)
        if ((long long)in_sizes[i] > mx) { mx = in_sizes[i]; idx_emb = i; }
    long long mx2 = -1;
    for (int i = 0; i < n_in; i++) {
        if (i == idx_emb) continue;
        if ((long long)in_sizes[i] > mx2) { mx2 = in_sizes[i]; idx_ei = i; }
    }
    for (int i = 0; i < n_in; i++) {
        if (i == idx_emb || i == idx_ei) continue;
        if (idx_s0 < 0) idx_s0 = i; else idx_s1 = i;
    }

    const float4* emb   = (const float4*)d_in[idx_emb];
    const void*   ei    = d_in[idx_ei];
    const int4*   cand0 = (const int4*)d_in[idx_s0];
    const int4*   cand1 = (const int4*)d_in[idx_s1];
    float4*       out   = (float4*)d_out;

    // E from edge_emb element count: immune to i64-vs-i32 size conventions.
    int E = in_sizes[idx_emb] / EM_DIM;    // 409600

    k_prep<<<(M_TOT / 4 + 255) / 256, 256>>>(cand0, cand1, (const int*)ei);
    k_match<<<(E / 2 + 255) / 256, 256>>>(ei, E);
    k_gather<<<NUM_INST, EM_DIM>>>(emb, out);
}